// round 16
// baseline (speedup 1.0000x reference)
#include <cuda_runtime.h>
#include <cuda_fp16.h>
#include <cstdint>

#define Dh   2048
#define NEXP 8
#define NTOK 2048
#define NASSIGN 4096
#define NSLOT 6144
#define BM 128
#define BN 64
#define BK 64
#define NKT (Dh/BK)
#define ASZ (128*64)            // A tile elems (fp16), swizzled stride 64
#define BSZ (64*64)             // B tile elems
#define K1_STAGE (ASZ + 2*BSZ)  // A | Gh Uh = 16384 elems (32 KB)
#define K2_STAGE (ASZ + BSZ)    // A | Bh = 12288 elems (24 KB)
#define K1_SMEM (3*K1_STAGE*2)  // 98304 B  (2 CTAs/SM)
#define K2_SMEM (3*K2_STAGE*2)  // 73728 B  (3 CTAs/SM)

// ---------------- device scratch ----------------
__device__ int g_counts[NEXP];
__device__ int g_offsets[NEXP];
__device__ int g_rowmap[NASSIGN];
__device__ int g_slotmap[NASSIGN];
__device__ __align__(16) __half g_x[(size_t)NTOK * Dh];
__device__ __align__(16) __half g_gate[(size_t)NEXP * Dh * Dh];
__device__ __align__(16) __half g_up[(size_t)NEXP * Dh * Dh];
__device__ __align__(16) __half g_dn[(size_t)NEXP * Dh * Dh];
__device__ __align__(16) __half g_sg[(size_t)Dh * Dh];
__device__ __align__(16) __half g_su[(size_t)Dh * Dh];
__device__ __align__(16) __half g_sd[(size_t)Dh * Dh];
__device__ __align__(16) __half g_act[(size_t)NSLOT * Dh];
__device__ __align__(16) float g_ys[(size_t)NSLOT * Dh];

// ---------------- helpers ----------------
__device__ __forceinline__ unsigned pkh(__half a, __half b) {
    return (unsigned)__half_as_ushort(a) | ((unsigned)__half_as_ushort(b) << 16);
}
__device__ __forceinline__ void mma_f16(float c[4], const unsigned a[4], const unsigned* b) {
    asm volatile(
        "mma.sync.aligned.m16n8k16.row.col.f32.f16.f16.f32 "
        "{%0,%1,%2,%3},{%4,%5,%6,%7},{%8,%9},{%0,%1,%2,%3};\n"
        : "+f"(c[0]), "+f"(c[1]), "+f"(c[2]), "+f"(c[3])
        : "r"(a[0]), "r"(a[1]), "r"(a[2]), "r"(a[3]), "r"(b[0]), "r"(b[1]));
}
__device__ __forceinline__ void cp16(__half* dst, const __half* src, bool p) {
    unsigned d = (unsigned)__cvta_generic_to_shared(dst);
    int sz = p ? 16 : 0;
    asm volatile("cp.async.cg.shared.global [%0], [%1], 16, %2;\n" :: "r"(d), "l"(src), "r"(sz));
}
#define CP_COMMIT() asm volatile("cp.async.commit_group;\n" ::: "memory")
#define CP_WAIT1()  asm volatile("cp.async.wait_group 1;\n" ::: "memory")
#define LDSM4(r, a) \
    asm volatile("ldmatrix.sync.aligned.m8n8.x4.shared.b16 {%0,%1,%2,%3}, [%4];" \
        : "=r"((r)[0]), "=r"((r)[1]), "=r"((r)[2]), "=r"((r)[3]) : "r"(a))

// XOR swizzle: elem offset of 16B chunk `ch` (0..7) in row `row` (stride 64 elems)
__device__ __forceinline__ int sw(int row, int ch) {
    return row * 64 + (((ch) ^ (row & 7)) << 3);
}

// ---------------- fused fp32 -> fp16 conversion (hi only, ONE launch) ----------------
struct CvtArgs {
    const float* src[7];
    __half* hi[7];
    long n4[7];
};
__global__ void __launch_bounds__(256) cvt_all_kernel(CvtArgs a, long total4) {
    long i = (long)blockIdx.x * blockDim.x + threadIdx.x;
    if (i >= total4) return;
    long off = 0;
#pragma unroll
    for (int r = 0; r < 7; r++) {
        if (i < off + a.n4[r]) {
            long j = i - off;
            float4 v = ((const float4*)a.src[r])[j];
            ((uint2*)a.hi[r])[j] = make_uint2(
                pkh(__float2half_rn(v.x), __float2half_rn(v.y)),
                pkh(__float2half_rn(v.z), __float2half_rn(v.w)));
            return;
        }
        off += a.n4[r];
    }
}

// ---------------- fused routing (ONE launch) ----------------
__global__ void route_all_kernel(const int* __restrict__ idx) {
    __shared__ int cnt[NEXP], off[NEXP], cur[NEXP];
    int tid = threadIdx.x;
    if (tid < NEXP) { cnt[tid] = 0; cur[tid] = 0; }
    __syncthreads();
    for (int i = tid; i < NASSIGN; i += 256) {
        int e = idx[i];
        if (e < 0) e = 0; if (e >= NEXP) e = NEXP - 1;
        atomicAdd(&cnt[e], 1);
    }
    __syncthreads();
    if (tid == 0) {
        int acc = 0;
        for (int e = 0; e < NEXP; e++) { off[e] = acc; acc += cnt[e]; }
    }
    __syncthreads();
    for (int i = tid; i < NASSIGN; i += 256) {
        int e = idx[i];
        if (e < 0) e = 0; if (e >= NEXP) e = NEXP - 1;
        int pos = off[e] + atomicAdd(&cur[e], 1);
        g_rowmap[pos] = i >> 1;
        g_slotmap[i] = pos;
    }
    if (tid < NEXP) { g_counts[tid] = cnt[tid]; g_offsets[tid] = off[tid]; }
}

// one dummy so moe_k1 = program launch #6 (ncu -s 5 -c 1)
__global__ void dummy_kernel() {}

// ---------------- K1: gate/up GEMMs + SiLU -> act fp16 (LDSM fragments) ----------------
__global__ void __launch_bounds__(128, 2) moe_k1() {
    const int seg = blockIdx.z;
    const int cnt = (seg == NEXP) ? NTOK : g_counts[seg];
    const int mtile = blockIdx.y;
    if (mtile * BM >= cnt) return;
    const int ntile = blockIdx.x;
    const int segbase = (seg == NEXP) ? NASSIGN : g_offsets[seg];

    const __half *gw, *uw;
    if (seg == NEXP) { gw = g_sg; uw = g_su; }
    else {
        size_t off = (size_t)seg * Dh * Dh;
        gw = g_gate + off; uw = g_up + off;
    }

    extern __shared__ __align__(16) __half sm[];
    __shared__ int stok[BM];

    const int tid = threadIdx.x, wid = tid >> 5, lane = tid & 31;
    {
        int r = mtile * BM + tid;
        stok[tid] = (r < cnt) ? ((seg == NEXP) ? r : g_rowmap[segbase + r]) : -1;
    }
    __syncthreads();

    const int gid = lane >> 2, tg = lane & 3;
    const int wm = wid >> 1, wn = wid & 1;
    const int lj = lane >> 3, lr = lane & 7;   // LDSM lane decomposition
    const unsigned sm_u = (unsigned)__cvta_generic_to_shared(sm);

    float accg[4][4][4], accu[4][4][4];
#pragma unroll
    for (int mi = 0; mi < 4; mi++)
#pragma unroll
        for (int ni = 0; ni < 4; ni++)
#pragma unroll
            for (int j = 0; j < 4; j++) { accg[mi][ni][j] = 0.f; accu[mi][ni][j] = 0.f; }

    auto issue = [&](int st, int k0) {
        __half* base = sm + st * K1_STAGE;
#pragma unroll
        for (int i = 0; i < 8; i++) {
            int c = tid + i * 128; int row = c >> 3, ch = c & 7;
            int tok = stok[row]; bool p = tok >= 0;
            size_t so = (size_t)(p ? tok : 0) * Dh + k0 + ch * 8;
            cp16(base + sw(row, ch), g_x + so, p);
        }
#pragma unroll
        for (int i = 0; i < 4; i++) {
            int c = tid + i * 128; int row = c >> 3, ch = c & 7;
            size_t bo = (size_t)(ntile * BN + row) * Dh + k0 + ch * 8;
            int dst = sw(row, ch);
            __half* bb = base + ASZ;
            cp16(bb + dst,       gw + bo, true);
            cp16(bb + BSZ + dst, uw + bo, true);
        }
    };

    issue(0, 0);       CP_COMMIT();
    issue(1, BK);      CP_COMMIT();
    for (int j = 0; j < NKT; j++) {
        const int s = j % 3;
        CP_WAIT1();
        __syncthreads();
        if (j + 2 < NKT) { issue((j + 2) % 3, (j + 2) * BK); CP_COMMIT(); }
        else { CP_COMMIT(); }

        const unsigned A_u = sm_u + (unsigned)(s * K1_STAGE) * 2u;
        const unsigned G_u = A_u + ASZ * 2u;
        const unsigned U_u = G_u + BSZ * 2u;

#pragma unroll
        for (int ks = 0; ks < 4; ks++) {
            // A fragments: matrices (ra,2ks),(rb,2ks),(ra,2ks+1),(rb,2ks+1)
            unsigned ah[4][4];
#pragma unroll
            for (int mi = 0; mi < 4; mi++) {
                int r = wm * 64 + mi * 16 + ((lj & 1) << 3) + lr;
                int ch = 2 * ks + (lj >> 1);
                LDSM4(ah[mi], A_u + (unsigned)sw(r, ch) * 2u);
            }
            // B fragments: one LDSM4 per ni-pair: (n0,2ks),(n0,2ks+1),(n0+8,2ks),(n0+8,2ks+1)
            unsigned bg[2][4], bu[2][4];
#pragma unroll
            for (int p = 0; p < 2; p++) {
                int n = wn * 32 + p * 16 + ((lj >> 1) << 3) + lr;
                int ch = 2 * ks + (lj & 1);
                unsigned off = (unsigned)sw(n, ch) * 2u;
                LDSM4(bg[p], G_u + off);
                LDSM4(bu[p], U_u + off);
            }
#pragma unroll
            for (int p = 0; p < 2; p++)
#pragma unroll
                for (int q = 0; q < 2; q++) {
                    int ni = 2 * p + q;
#pragma unroll
                    for (int mi = 0; mi < 4; mi++) {
                        mma_f16(accg[mi][ni], ah[mi], &bg[p][q * 2]);
                        mma_f16(accu[mi][ni], ah[mi], &bu[p][q * 2]);
                    }
                }
        }
    }

    // epilogue: act = silu(gate)*up -> fp16
#pragma unroll
    for (int mi = 0; mi < 4; mi++) {
#pragma unroll
        for (int h = 0; h < 2; h++) {
            int rl = mtile * BM + wm * 64 + mi * 16 + gid + h * 8;
            if (rl < cnt) {
                size_t rowoff = (size_t)(segbase + rl) * Dh;
#pragma unroll
                for (int ni = 0; ni < 4; ni++) {
                    int c = ntile * BN + wn * 32 + ni * 8 + tg * 2;
                    float g0 = accg[mi][ni][h * 2 + 0], g1 = accg[mi][ni][h * 2 + 1];
                    float u0 = accu[mi][ni][h * 2 + 0], u1 = accu[mi][ni][h * 2 + 1];
                    float a0 = g0 * u0 / (1.f + __expf(-g0));
                    float a1 = g1 * u1 / (1.f + __expf(-g1));
                    *(unsigned*)&g_act[rowoff + c] = pkh(__float2half_rn(a0), __float2half_rn(a1));
                }
            }
        }
    }
}

// ---------------- K2: y = act @ down_w^T (LDSM fragments, 3 CTAs/SM) ----------------
__global__ void __launch_bounds__(128, 3) moe_k2() {
    const int seg = blockIdx.z;
    const int cnt = (seg == NEXP) ? NTOK : g_counts[seg];
    const int mtile = blockIdx.y;
    if (mtile * BM >= cnt) return;
    const int ntile = blockIdx.x;
    const int segbase = (seg == NEXP) ? NASSIGN : g_offsets[seg];

    const __half* dw = (seg == NEXP) ? g_sd : g_dn + (size_t)seg * Dh * Dh;

    extern __shared__ __align__(16) __half sm[];

    const int tid = threadIdx.x, wid = tid >> 5, lane = tid & 31;
    const int gid = lane >> 2, tg = lane & 3;
    const int wm = wid >> 1, wn = wid & 1;
    const int lj = lane >> 3, lr = lane & 7;
    const unsigned sm_u = (unsigned)__cvta_generic_to_shared(sm);

    float acc[4][4][4];
#pragma unroll
    for (int mi = 0; mi < 4; mi++)
#pragma unroll
        for (int ni = 0; ni < 4; ni++)
#pragma unroll
            for (int j = 0; j < 4; j++) acc[mi][ni][j] = 0.f;

    auto issue = [&](int st, int k0) {
        __half* base = sm + st * K2_STAGE;
#pragma unroll
        for (int i = 0; i < 8; i++) {
            int c = tid + i * 128; int row = c >> 3, ch = c & 7;
            int grow = mtile * BM + row; bool p = grow < cnt;
            size_t so = (size_t)(segbase + (p ? grow : 0)) * Dh + k0 + ch * 8;
            cp16(base + sw(row, ch), g_act + so, p);
        }
#pragma unroll
        for (int i = 0; i < 4; i++) {
            int c = tid + i * 128; int row = c >> 3, ch = c & 7;
            size_t bo = (size_t)(ntile * BN + row) * Dh + k0 + ch * 8;
            cp16(base + ASZ + sw(row, ch), dw + bo, true);
        }
    };

    issue(0, 0);       CP_COMMIT();
    issue(1, BK);      CP_COMMIT();
    for (int j = 0; j < NKT; j++) {
        const int s = j % 3;
        CP_WAIT1();
        __syncthreads();
        if (j + 2 < NKT) { issue((j + 2) % 3, (j + 2) * BK); CP_COMMIT(); }
        else { CP_COMMIT(); }

        const unsigned A_u = sm_u + (unsigned)(s * K2_STAGE) * 2u;
        const unsigned B_u = A_u + ASZ * 2u;

#pragma unroll
        for (int ks = 0; ks < 4; ks++) {
            unsigned ah[4][4];
#pragma unroll
            for (int mi = 0; mi < 4; mi++) {
                int r = wm * 64 + mi * 16 + ((lj & 1) << 3) + lr;
                int ch = 2 * ks + (lj >> 1);
                LDSM4(ah[mi], A_u + (unsigned)sw(r, ch) * 2u);
            }
            unsigned bh[2][4];
#pragma unroll
            for (int p = 0; p < 2; p++) {
                int n = wn * 32 + p * 16 + ((lj >> 1) << 3) + lr;
                int ch = 2 * ks + (lj & 1);
                LDSM4(bh[p], B_u + (unsigned)sw(n, ch) * 2u);
            }
#pragma unroll
            for (int p = 0; p < 2; p++)
#pragma unroll
                for (int q = 0; q < 2; q++) {
                    int ni = 2 * p + q;
#pragma unroll
                    for (int mi = 0; mi < 4; mi++)
                        mma_f16(acc[mi][ni], ah[mi], &bh[p][q * 2]);
                }
        }
    }

#pragma unroll
    for (int mi = 0; mi < 4; mi++) {
#pragma unroll
        for (int h = 0; h < 2; h++) {
            int rl = mtile * BM + wm * 64 + mi * 16 + gid + h * 8;
            if (rl < cnt) {
                size_t rowoff = (size_t)(segbase + rl) * Dh;
#pragma unroll
                for (int ni = 0; ni < 4; ni++) {
                    int c = ntile * BN + wn * 32 + ni * 8 + tg * 2;
                    float2 v = make_float2(acc[mi][ni][h * 2 + 0], acc[mi][ni][h * 2 + 1]);
                    *(float2*)&g_ys[rowoff + c] = v;
                }
            }
        }
    }
}

// ---------------- combine ----------------
__global__ void combine_kernel(const float* __restrict__ weights, float* __restrict__ out) {
    int idx = blockIdx.x * blockDim.x + threadIdx.x;
    if (idx >= NTOK * (Dh / 4)) return;
    int t = idx / (Dh / 4);
    int c4 = idx % (Dh / 4);
    float4 r = *(const float4*)&g_ys[(size_t)(NASSIGN + t) * Dh + c4 * 4];
    int p0 = g_slotmap[2 * t], p1 = g_slotmap[2 * t + 1];
    float w0 = weights[2 * t], w1 = weights[2 * t + 1];
    float4 y0 = *(const float4*)&g_ys[(size_t)p0 * Dh + c4 * 4];
    float4 y1 = *(const float4*)&g_ys[(size_t)p1 * Dh + c4 * 4];
    r.x += w0 * y0.x + w1 * y1.x;
    r.y += w0 * y0.y + w1 * y1.y;
    r.z += w0 * y0.z + w1 * y1.z;
    r.w += w0 * y0.w + w1 * y1.w;
    *(float4*)&out[(size_t)t * Dh + c4 * 4] = r;
}

extern "C" void kernel_launch(void* const* d_in, const int* in_sizes, int n_in,
                              void* d_out, int out_size) {
    const float* x        = (const float*)d_in[0];
    const float* weights  = (const float*)d_in[1];
    const int* idx        = (const int*)d_in[2];   // int32 (jax x64 disabled)
    const float* gate_w   = (const float*)d_in[5];
    const float* up_w     = (const float*)d_in[6];
    const float* down_w   = (const float*)d_in[7];
    const float* sgw      = (const float*)d_in[8];
    const float* suw      = (const float*)d_in[9];
    const float* sdw      = (const float*)d_in[10];
    float* out = (float*)d_out;

    cudaFuncSetAttribute(moe_k1, cudaFuncAttributeMaxDynamicSharedMemorySize, K1_SMEM);
    cudaFuncSetAttribute(moe_k2, cudaFuncAttributeMaxDynamicSharedMemorySize, K2_SMEM);

    // launch 1: fused conversion (all tensors -> fp16)
    {
        CvtArgs a;
        const float* srcs[7] = { x, gate_w, up_w, down_w, sgw, suw, sdw };
        void* his[7];
        cudaGetSymbolAddress(&his[0], g_x);
        cudaGetSymbolAddress(&his[1], g_gate);
        cudaGetSymbolAddress(&his[2], g_up);
        cudaGetSymbolAddress(&his[3], g_dn);
        cudaGetSymbolAddress(&his[4], g_sg);
        cudaGetSymbolAddress(&his[5], g_su);
        cudaGetSymbolAddress(&his[6], g_sd);
        long n4s[7] = {
            (long)NTOK * Dh / 4,
            (long)NEXP * Dh * Dh / 4, (long)NEXP * Dh * Dh / 4, (long)NEXP * Dh * Dh / 4,
            (long)Dh * Dh / 4, (long)Dh * Dh / 4, (long)Dh * Dh / 4
        };
        long total4 = 0;
        for (int r = 0; r < 7; r++) {
            a.src[r] = srcs[r];
            a.hi[r] = (__half*)his[r];
            a.n4[r] = n4s[r];
            total4 += n4s[r];
        }
        cvt_all_kernel<<<(unsigned)((total4 + 255) / 256), 256>>>(a, total4);
    }

    // launch 2: fused routing
    route_all_kernel<<<1, 256>>>(idx);

    // launch 3: dummy (keeps moe_k1 at program launch #6 for ncu)
    dummy_kernel<<<1, 32>>>();

    // launches 4-5: GEMMs
    dim3 grid(Dh / BN, 32, NEXP + 1);
    moe_k1<<<grid, 128, K1_SMEM>>>();
    moe_k2<<<grid, 128, K2_SMEM>>>();

    // launch 6: combine
    combine_kernel<<<(NTOK * (Dh / 4) + 255) / 256, 256>>>(weights, out);
}

// round 17
// speedup vs baseline: 1.4091x; 1.4091x over previous
#include <cuda_runtime.h>
#include <cuda_fp16.h>
#include <cstdint>

#define Dh   2048
#define NEXP 8
#define NTOK 2048
#define NASSIGN 4096
#define NSLOT 6144
#define BM 128
#define BN 64
#define BK 64
#define NKT (Dh/BK)
#define ASZ (128*64)            // A tile elems (fp16), swizzled stride 64
#define BSZ (64*64)             // B tile elems
#define K1_STAGE (ASZ + 2*BSZ)  // A | Gh Uh = 16384 elems (32 KB)
#define K2_STAGE (ASZ + BSZ)    // A | Bh = 12288 elems (24 KB)
#define K1_SMEM (3*K1_STAGE*2)  // 98304 B  (2 CTAs/SM)
#define K2_SMEM (3*K2_STAGE*2)  // 73728 B  (3 CTAs/SM)

// ---------------- device scratch ----------------
__device__ int g_counts[NEXP];
__device__ int g_offsets[NEXP];
__device__ int g_rowmap[NASSIGN];
__device__ int g_slotmap[NASSIGN];
__device__ __align__(16) __half g_x[(size_t)NTOK * Dh];
__device__ __align__(16) __half g_gate[(size_t)NEXP * Dh * Dh];
__device__ __align__(16) __half g_up[(size_t)NEXP * Dh * Dh];
__device__ __align__(16) __half g_dn[(size_t)NEXP * Dh * Dh];
__device__ __align__(16) __half g_sg[(size_t)Dh * Dh];
__device__ __align__(16) __half g_su[(size_t)Dh * Dh];
__device__ __align__(16) __half g_sd[(size_t)Dh * Dh];
__device__ __align__(16) __half g_act[(size_t)NSLOT * Dh];
__device__ __align__(16) float g_ys[(size_t)NSLOT * Dh];

// ---------------- helpers ----------------
__device__ __forceinline__ unsigned pkh(__half a, __half b) {
    return (unsigned)__half_as_ushort(a) | ((unsigned)__half_as_ushort(b) << 16);
}
__device__ __forceinline__ void mma_f16(float c[4], const unsigned a[4], const unsigned b[2]) {
    asm volatile(
        "mma.sync.aligned.m16n8k16.row.col.f32.f16.f16.f32 "
        "{%0,%1,%2,%3},{%4,%5,%6,%7},{%8,%9},{%0,%1,%2,%3};\n"
        : "+f"(c[0]), "+f"(c[1]), "+f"(c[2]), "+f"(c[3])
        : "r"(a[0]), "r"(a[1]), "r"(a[2]), "r"(a[3]), "r"(b[0]), "r"(b[1]));
}
__device__ __forceinline__ void cp16(__half* dst, const __half* src, bool p) {
    unsigned d = (unsigned)__cvta_generic_to_shared(dst);
    int sz = p ? 16 : 0;
    asm volatile("cp.async.cg.shared.global [%0], [%1], 16, %2;\n" :: "r"(d), "l"(src), "r"(sz));
}
#define CP_COMMIT() asm volatile("cp.async.commit_group;\n" ::: "memory")
#define CP_WAIT1()  asm volatile("cp.async.wait_group 1;\n" ::: "memory")

// XOR swizzle: elem offset of 16B chunk `ch` (0..7) in row `row` (stride 64 elems)
__device__ __forceinline__ int sw(int row, int ch) {
    return row * 64 + (((ch) ^ (row & 7)) << 3);
}

// ---------------- fused fp32 -> fp16 conversion (hi only, ONE launch, MLP=2) ----------------
struct CvtArgs {
    const float* src[7];
    __half* hi[7];
    long n4[7];
};
__global__ void __launch_bounds__(256) cvt_all_kernel(CvtArgs a, long total8) {
    long i = (long)blockIdx.x * blockDim.x + threadIdx.x;   // one i = 2 float4
    if (i >= total8) return;
    long off = 0;
#pragma unroll
    for (int r = 0; r < 7; r++) {
        long n8 = a.n4[r] >> 1;
        if (i < off + n8) {
            long j = (i - off) * 2;
            const float4* s = (const float4*)a.src[r];
            float4 v0 = s[j];
            float4 v1 = s[j + 1];   // both loads in flight before stores
            uint2* d = (uint2*)a.hi[r];
            d[j] = make_uint2(pkh(__float2half_rn(v0.x), __float2half_rn(v0.y)),
                              pkh(__float2half_rn(v0.z), __float2half_rn(v0.w)));
            d[j + 1] = make_uint2(pkh(__float2half_rn(v1.x), __float2half_rn(v1.y)),
                                  pkh(__float2half_rn(v1.z), __float2half_rn(v1.w)));
            return;
        }
        off += n8;
    }
}

// ---------------- fused routing (ONE launch) ----------------
__global__ void route_all_kernel(const int* __restrict__ idx) {
    __shared__ int cnt[NEXP], off[NEXP], cur[NEXP];
    int tid = threadIdx.x;
    if (tid < NEXP) { cnt[tid] = 0; cur[tid] = 0; }
    __syncthreads();
    for (int i = tid; i < NASSIGN; i += 256) {
        int e = idx[i];
        if (e < 0) e = 0; if (e >= NEXP) e = NEXP - 1;
        atomicAdd(&cnt[e], 1);
    }
    __syncthreads();
    if (tid == 0) {
        int acc = 0;
        for (int e = 0; e < NEXP; e++) { off[e] = acc; acc += cnt[e]; }
    }
    __syncthreads();
    for (int i = tid; i < NASSIGN; i += 256) {
        int e = idx[i];
        if (e < 0) e = 0; if (e >= NEXP) e = NEXP - 1;
        int pos = off[e] + atomicAdd(&cur[e], 1);
        g_rowmap[pos] = i >> 1;
        g_slotmap[i] = pos;
    }
    if (tid < NEXP) { g_counts[tid] = cnt[tid]; g_offsets[tid] = off[tid]; }
}

// one dummy so moe_k1 = program launch #6 (ncu -s 5 -c 1)
__global__ void dummy_kernel() {}

// ---------------- K1: gate/up GEMMs + SiLU -> act fp16 (R14-proven: scalar LDS) ----------------
__global__ void __launch_bounds__(128, 2) moe_k1() {
    const int seg = blockIdx.z;
    const int cnt = (seg == NEXP) ? NTOK : g_counts[seg];
    const int mtile = blockIdx.y;
    if (mtile * BM >= cnt) return;
    const int ntile = blockIdx.x;
    const int segbase = (seg == NEXP) ? NASSIGN : g_offsets[seg];

    const __half *gw, *uw;
    if (seg == NEXP) { gw = g_sg; uw = g_su; }
    else {
        size_t off = (size_t)seg * Dh * Dh;
        gw = g_gate + off; uw = g_up + off;
    }

    extern __shared__ __align__(16) __half sm[];
    __shared__ int stok[BM];

    const int tid = threadIdx.x, wid = tid >> 5, lane = tid & 31;
    {
        int r = mtile * BM + tid;
        stok[tid] = (r < cnt) ? ((seg == NEXP) ? r : g_rowmap[segbase + r]) : -1;
    }
    __syncthreads();

    const int gid = lane >> 2, tg = lane & 3;
    const int wm = wid >> 1, wn = wid & 1;

    float accg[4][4][4], accu[4][4][4];
#pragma unroll
    for (int mi = 0; mi < 4; mi++)
#pragma unroll
        for (int ni = 0; ni < 4; ni++)
#pragma unroll
            for (int j = 0; j < 4; j++) { accg[mi][ni][j] = 0.f; accu[mi][ni][j] = 0.f; }

    auto issue = [&](int st, int k0) {
        __half* base = sm + st * K1_STAGE;
#pragma unroll
        for (int i = 0; i < 8; i++) {
            int c = tid + i * 128; int row = c >> 3, ch = c & 7;
            int tok = stok[row]; bool p = tok >= 0;
            size_t so = (size_t)(p ? tok : 0) * Dh + k0 + ch * 8;
            cp16(base + sw(row, ch), g_x + so, p);
        }
#pragma unroll
        for (int i = 0; i < 4; i++) {
            int c = tid + i * 128; int row = c >> 3, ch = c & 7;
            size_t bo = (size_t)(ntile * BN + row) * Dh + k0 + ch * 8;
            int dst = sw(row, ch);
            __half* bb = base + ASZ;
            cp16(bb + dst,       gw + bo, true);
            cp16(bb + BSZ + dst, uw + bo, true);
        }
    };

    issue(0, 0);       CP_COMMIT();
    issue(1, BK);      CP_COMMIT();
    for (int j = 0; j < NKT; j++) {
        const int s = j % 3;
        CP_WAIT1();
        __syncthreads();
        if (j + 2 < NKT) { issue((j + 2) % 3, (j + 2) * BK); CP_COMMIT(); }
        else { CP_COMMIT(); }

        const __half* A  = sm + s * K1_STAGE;
        const __half* Gh = A + ASZ;
        const __half* Uh = Gh + BSZ;

#pragma unroll
        for (int ks = 0; ks < 4; ks++) {
            unsigned ah[4][4];
#pragma unroll
            for (int mi = 0; mi < 4; mi++) {
                int ra = wm * 64 + mi * 16 + gid, rb = ra + 8;
                ah[mi][0] = *(const unsigned*)&A[sw(ra, 2 * ks) + tg * 2];
                ah[mi][1] = *(const unsigned*)&A[sw(rb, 2 * ks) + tg * 2];
                ah[mi][2] = *(const unsigned*)&A[sw(ra, 2 * ks + 1) + tg * 2];
                ah[mi][3] = *(const unsigned*)&A[sw(rb, 2 * ks + 1) + tg * 2];
            }
#pragma unroll
            for (int ni = 0; ni < 4; ni++) {
                int n = wn * 32 + ni * 8 + gid;
                unsigned bg[2], bu[2];
                bg[0] = *(const unsigned*)&Gh[sw(n, 2 * ks) + tg * 2];
                bg[1] = *(const unsigned*)&Gh[sw(n, 2 * ks + 1) + tg * 2];
                bu[0] = *(const unsigned*)&Uh[sw(n, 2 * ks) + tg * 2];
                bu[1] = *(const unsigned*)&Uh[sw(n, 2 * ks + 1) + tg * 2];
#pragma unroll
                for (int mi = 0; mi < 4; mi++) {
                    mma_f16(accg[mi][ni], ah[mi], bg);
                    mma_f16(accu[mi][ni], ah[mi], bu);
                }
            }
        }
    }

    // epilogue: act = silu(gate)*up -> fp16
#pragma unroll
    for (int mi = 0; mi < 4; mi++) {
#pragma unroll
        for (int h = 0; h < 2; h++) {
            int rl = mtile * BM + wm * 64 + mi * 16 + gid + h * 8;
            if (rl < cnt) {
                size_t rowoff = (size_t)(segbase + rl) * Dh;
#pragma unroll
                for (int ni = 0; ni < 4; ni++) {
                    int c = ntile * BN + wn * 32 + ni * 8 + tg * 2;
                    float g0 = accg[mi][ni][h * 2 + 0], g1 = accg[mi][ni][h * 2 + 1];
                    float u0 = accu[mi][ni][h * 2 + 0], u1 = accu[mi][ni][h * 2 + 1];
                    float a0 = g0 * u0 / (1.f + __expf(-g0));
                    float a1 = g1 * u1 / (1.f + __expf(-g1));
                    *(unsigned*)&g_act[rowoff + c] = pkh(__float2half_rn(a0), __float2half_rn(a1));
                }
            }
        }
    }
}

// ---------------- K2: y = act @ down_w^T (R14-proven, 3 CTAs/SM) ----------------
__global__ void __launch_bounds__(128, 3) moe_k2() {
    const int seg = blockIdx.z;
    const int cnt = (seg == NEXP) ? NTOK : g_counts[seg];
    const int mtile = blockIdx.y;
    if (mtile * BM >= cnt) return;
    const int ntile = blockIdx.x;
    const int segbase = (seg == NEXP) ? NASSIGN : g_offsets[seg];

    const __half* dw = (seg == NEXP) ? g_sd : g_dn + (size_t)seg * Dh * Dh;

    extern __shared__ __align__(16) __half sm[];

    const int tid = threadIdx.x, wid = tid >> 5, lane = tid & 31;
    const int gid = lane >> 2, tg = lane & 3;
    const int wm = wid >> 1, wn = wid & 1;

    float acc[4][4][4];
#pragma unroll
    for (int mi = 0; mi < 4; mi++)
#pragma unroll
        for (int ni = 0; ni < 4; ni++)
#pragma unroll
            for (int j = 0; j < 4; j++) acc[mi][ni][j] = 0.f;

    auto issue = [&](int st, int k0) {
        __half* base = sm + st * K2_STAGE;
#pragma unroll
        for (int i = 0; i < 8; i++) {
            int c = tid + i * 128; int row = c >> 3, ch = c & 7;
            int grow = mtile * BM + row; bool p = grow < cnt;
            size_t so = (size_t)(segbase + (p ? grow : 0)) * Dh + k0 + ch * 8;
            cp16(base + sw(row, ch), g_act + so, p);
        }
#pragma unroll
        for (int i = 0; i < 4; i++) {
            int c = tid + i * 128; int row = c >> 3, ch = c & 7;
            size_t bo = (size_t)(ntile * BN + row) * Dh + k0 + ch * 8;
            cp16(base + ASZ + sw(row, ch), dw + bo, true);
        }
    };

    issue(0, 0);       CP_COMMIT();
    issue(1, BK);      CP_COMMIT();
    for (int j = 0; j < NKT; j++) {
        const int s = j % 3;
        CP_WAIT1();
        __syncthreads();
        if (j + 2 < NKT) { issue((j + 2) % 3, (j + 2) * BK); CP_COMMIT(); }
        else { CP_COMMIT(); }

        const __half* A  = sm + s * K2_STAGE;
        const __half* Bh = A + ASZ;

#pragma unroll
        for (int ks = 0; ks < 4; ks++) {
            unsigned ah[4][4];
#pragma unroll
            for (int mi = 0; mi < 4; mi++) {
                int ra = wm * 64 + mi * 16 + gid, rb = ra + 8;
                ah[mi][0] = *(const unsigned*)&A[sw(ra, 2 * ks) + tg * 2];
                ah[mi][1] = *(const unsigned*)&A[sw(rb, 2 * ks) + tg * 2];
                ah[mi][2] = *(const unsigned*)&A[sw(ra, 2 * ks + 1) + tg * 2];
                ah[mi][3] = *(const unsigned*)&A[sw(rb, 2 * ks + 1) + tg * 2];
            }
#pragma unroll
            for (int ni = 0; ni < 4; ni++) {
                int n = wn * 32 + ni * 8 + gid;
                unsigned bh[2];
                bh[0] = *(const unsigned*)&Bh[sw(n, 2 * ks) + tg * 2];
                bh[1] = *(const unsigned*)&Bh[sw(n, 2 * ks + 1) + tg * 2];
#pragma unroll
                for (int mi = 0; mi < 4; mi++) {
                    mma_f16(acc[mi][ni], ah[mi], bh);
                }
            }
        }
    }

#pragma unroll
    for (int mi = 0; mi < 4; mi++) {
#pragma unroll
        for (int h = 0; h < 2; h++) {
            int rl = mtile * BM + wm * 64 + mi * 16 + gid + h * 8;
            if (rl < cnt) {
                size_t rowoff = (size_t)(segbase + rl) * Dh;
#pragma unroll
                for (int ni = 0; ni < 4; ni++) {
                    int c = ntile * BN + wn * 32 + ni * 8 + tg * 2;
                    float2 v = make_float2(acc[mi][ni][h * 2 + 0], acc[mi][ni][h * 2 + 1]);
                    *(float2*)&g_ys[rowoff + c] = v;
                }
            }
        }
    }
}

// ---------------- combine ----------------
__global__ void combine_kernel(const float* __restrict__ weights, float* __restrict__ out) {
    int idx = blockIdx.x * blockDim.x + threadIdx.x;
    if (idx >= NTOK * (Dh / 4)) return;
    int t = idx / (Dh / 4);
    int c4 = idx % (Dh / 4);
    float4 r = *(const float4*)&g_ys[(size_t)(NASSIGN + t) * Dh + c4 * 4];
    int p0 = g_slotmap[2 * t], p1 = g_slotmap[2 * t + 1];
    float w0 = weights[2 * t], w1 = weights[2 * t + 1];
    float4 y0 = *(const float4*)&g_ys[(size_t)p0 * Dh + c4 * 4];
    float4 y1 = *(const float4*)&g_ys[(size_t)p1 * Dh + c4 * 4];
    r.x += w0 * y0.x + w1 * y1.x;
    r.y += w0 * y0.y + w1 * y1.y;
    r.z += w0 * y0.z + w1 * y1.z;
    r.w += w0 * y0.w + w1 * y1.w;
    *(float4*)&out[(size_t)t * Dh + c4 * 4] = r;
}

extern "C" void kernel_launch(void* const* d_in, const int* in_sizes, int n_in,
                              void* d_out, int out_size) {
    const float* x        = (const float*)d_in[0];
    const float* weights  = (const float*)d_in[1];
    const int* idx        = (const int*)d_in[2];   // int32 (jax x64 disabled)
    const float* gate_w   = (const float*)d_in[5];
    const float* up_w     = (const float*)d_in[6];
    const float* down_w   = (const float*)d_in[7];
    const float* sgw      = (const float*)d_in[8];
    const float* suw      = (const float*)d_in[9];
    const float* sdw      = (const float*)d_in[10];
    float* out = (float*)d_out;

    cudaFuncSetAttribute(moe_k1, cudaFuncAttributeMaxDynamicSharedMemorySize, K1_SMEM);
    cudaFuncSetAttribute(moe_k2, cudaFuncAttributeMaxDynamicSharedMemorySize, K2_SMEM);

    // launch 1: fused conversion (all tensors -> fp16), 2 float4 per thread
    {
        CvtArgs a;
        const float* srcs[7] = { x, gate_w, up_w, down_w, sgw, suw, sdw };
        void* his[7];
        cudaGetSymbolAddress(&his[0], g_x);
        cudaGetSymbolAddress(&his[1], g_gate);
        cudaGetSymbolAddress(&his[2], g_up);
        cudaGetSymbolAddress(&his[3], g_dn);
        cudaGetSymbolAddress(&his[4], g_sg);
        cudaGetSymbolAddress(&his[5], g_su);
        cudaGetSymbolAddress(&his[6], g_sd);
        long n4s[7] = {
            (long)NTOK * Dh / 4,
            (long)NEXP * Dh * Dh / 4, (long)NEXP * Dh * Dh / 4, (long)NEXP * Dh * Dh / 4,
            (long)Dh * Dh / 4, (long)Dh * Dh / 4, (long)Dh * Dh / 4
        };
        long total8 = 0;
        for (int r = 0; r < 7; r++) {
            a.src[r] = srcs[r];
            a.hi[r] = (__half*)his[r];
            a.n4[r] = n4s[r];
            total8 += n4s[r] >> 1;
        }
        cvt_all_kernel<<<(unsigned)((total8 + 255) / 256), 256>>>(a, total8);
    }

    // launch 2: fused routing
    route_all_kernel<<<1, 256>>>(idx);

    // launch 3: dummy (keeps moe_k1 at program launch #6 for ncu)
    dummy_kernel<<<1, 32>>>();

    // launches 4-5: GEMMs
    dim3 grid(Dh / BN, 32, NEXP + 1);
    moe_k1<<<grid, 128, K1_SMEM>>>();
    moe_k2<<<grid, 128, K2_SMEM>>>();

    // launch 6: combine
    combine_kernel<<<(NTOK * (Dh / 4) + 255) / 256, 256>>>(weights, out);
}